// round 7
// baseline (speedup 1.0000x reference)
#include <cuda_runtime.h>
#include <math_constants.h>

__device__ unsigned g_maxu;   // ordered-uint global max; zero-init (< any encoded real), monotone
__device__ unsigned g_count;  // zero-init; last block resets to 0 each call

__device__ __forceinline__ unsigned order_f32(float f) {
    unsigned u = __float_as_uint(f);
    return (u & 0x80000000u) ? ~u : (u | 0x80000000u);
}
__device__ __forceinline__ float unorder_f32(unsigned u) {
    return __uint_as_float((u & 0x80000000u) ? (u ^ 0x80000000u) : ~u);
}

__device__ __forceinline__ void top2_update(float& t1, float& t2, float v) {
    t2 = fmaxf(t2, fminf(t1, v));
    t1 = fmaxf(t1, v);
}

// One block (224 thr = 7 warps) per row. Warp h scans head h. One barrier.
// Global max via one atomicMax per block; last-done block writes out[0].
template<int NV4>   // NV4 = C/4
__global__ __launch_bounds__(224) void fused_kernel(
    const float* __restrict__ o1, const float* __restrict__ o2,
    const float* __restrict__ o3, const float* __restrict__ o4,
    const float* __restrict__ o5, const float* __restrict__ o6,
    const float* __restrict__ mimic,
    const int* __restrict__ targets,
    float* __restrict__ out_thresh,   // [N,7]
    float* __restrict__ out_max,      // out[0]
    int C)
{
    const int row  = blockIdx.x;
    const int wid  = threadIdx.x >> 5;   // 0..6
    const int lane = threadIdx.x & 31;

    __shared__ float s_margin[7];
    __shared__ float s_top1[7];

    const float* heads[7] = {o1, o2, o3, o4, o5, o6, mimic};
    const float* p = heads[wid] + (size_t)row * (size_t)C;
    const float4* p4 = (const float4*)p;

    // prefetch target value early (overlaps the bulk loads)
    float tval = (lane == 0) ? __ldg(p + targets[row]) : 0.0f;

    constexpr int K = (NV4 + 31) / 32;    // 8 for NV4=250
    float4 v[K];
    #pragma unroll
    for (int k = 0; k < K; ++k) {
        int idx = lane + 32 * k;
        if (32 * k + 31 < NV4 || idx < NV4)
            v[k] = __ldcs(p4 + idx);
        else
            v[k] = make_float4(-CUDART_INF_F, -CUDART_INF_F,
                               -CUDART_INF_F, -CUDART_INF_F);
    }

    float t1 = -CUDART_INF_F, t2 = -CUDART_INF_F;
    #pragma unroll
    for (int k = 0; k < K; ++k) {
        top2_update(t1, t2, v[k].x);
        top2_update(t1, t2, v[k].y);
        top2_update(t1, t2, v[k].z);
        top2_update(t1, t2, v[k].w);
    }

    #pragma unroll
    for (int off = 16; off; off >>= 1) {
        float u1 = __shfl_down_sync(0xFFFFFFFFu, t1, off);
        float u2 = __shfl_down_sync(0xFFFFFFFFu, t2, off);
        t2 = fmaxf(fmaxf(t2, u2), fminf(t1, u1));
        t1 = fmaxf(t1, u1);
    }

    if (lane == 0) {
        s_margin[wid] = (tval == t1) ? (t1 - t2) * 0.5f : 0.0f;
        s_top1[wid]   = t1;
    }
    __syncthreads();

    if (threadIdx.x == 0) {
        // row max over heads 0..5 -> single-slot atomicMax (ordered encoding)
        float bm = s_top1[0];
        #pragma unroll
        for (int h = 1; h < 6; ++h) bm = fmaxf(bm, s_top1[h]);
        atomicMax(&g_maxu, order_f32(bm));

        // 7-way softmax of pre-scaled margins
        float m[7], mx = -CUDART_INF_F;
        #pragma unroll
        for (int h = 0; h < 7; ++h) { m[h] = s_margin[h]; mx = fmaxf(mx, m[h]); }
        float e[7], sum = 0.0f;
        #pragma unroll
        for (int h = 0; h < 7; ++h) { e[h] = __expf(m[h] - mx); sum += e[h]; }
        float inv = 1.0f / sum;
        float* o = out_thresh + (size_t)row * 7;
        #pragma unroll
        for (int h = 0; h < 7; ++h) o[h] = e[h] * inv;

        // last-done block publishes the global max (tail cost ~= one L2 read)
        __threadfence();
        unsigned old = atomicAdd(&g_count, 1u);
        if (old == gridDim.x - 1) {
            out_max[0] = unorder_f32(g_maxu);
            g_count = 0;   // deterministic reset for next replay
        }
    }
}

// Generic fallback (runtime C), same structure.
__global__ __launch_bounds__(224) void fused_kernel_gen(
    const float* __restrict__ o1, const float* __restrict__ o2,
    const float* __restrict__ o3, const float* __restrict__ o4,
    const float* __restrict__ o5, const float* __restrict__ o6,
    const float* __restrict__ mimic,
    const int* __restrict__ targets,
    float* __restrict__ out_thresh, float* __restrict__ out_max,
    int C)
{
    const int row  = blockIdx.x;
    const int wid  = threadIdx.x >> 5;
    const int lane = threadIdx.x & 31;

    __shared__ float s_margin[7];
    __shared__ float s_top1[7];

    const float* heads[7] = {o1, o2, o3, o4, o5, o6, mimic};
    const float* p = heads[wid] + (size_t)row * (size_t)C;

    float tval = (lane == 0) ? __ldg(p + targets[row]) : 0.0f;

    float t1 = -CUDART_INF_F, t2 = -CUDART_INF_F;
    const int nv4 = C >> 2;
    const float4* p4 = (const float4*)p;
    for (int i = lane; i < nv4; i += 32) {
        float4 v = __ldcs(p4 + i);
        top2_update(t1, t2, v.x); top2_update(t1, t2, v.y);
        top2_update(t1, t2, v.z); top2_update(t1, t2, v.w);
    }
    for (int i = (nv4 << 2) + lane; i < C; i += 32)
        top2_update(t1, t2, p[i]);

    #pragma unroll
    for (int off = 16; off; off >>= 1) {
        float u1 = __shfl_down_sync(0xFFFFFFFFu, t1, off);
        float u2 = __shfl_down_sync(0xFFFFFFFFu, t2, off);
        t2 = fmaxf(fmaxf(t2, u2), fminf(t1, u1));
        t1 = fmaxf(t1, u1);
    }

    if (lane == 0) {
        s_margin[wid] = (tval == t1) ? (t1 - t2) * 0.5f : 0.0f;
        s_top1[wid]   = t1;
    }
    __syncthreads();

    if (threadIdx.x == 0) {
        float bm = s_top1[0];
        #pragma unroll
        for (int h = 1; h < 6; ++h) bm = fmaxf(bm, s_top1[h]);
        atomicMax(&g_maxu, order_f32(bm));

        float m[7], mx = -CUDART_INF_F;
        #pragma unroll
        for (int h = 0; h < 7; ++h) { m[h] = s_margin[h]; mx = fmaxf(mx, m[h]); }
        float e[7], sum = 0.0f;
        #pragma unroll
        for (int h = 0; h < 7; ++h) { e[h] = __expf(m[h] - mx); sum += e[h]; }
        float inv = 1.0f / sum;
        float* o = out_thresh + (size_t)row * 7;
        #pragma unroll
        for (int h = 0; h < 7; ++h) o[h] = e[h] * inv;

        __threadfence();
        unsigned old = atomicAdd(&g_count, 1u);
        if (old == gridDim.x - 1) {
            out_max[0] = unorder_f32(g_maxu);
            g_count = 0;
        }
    }
}

extern "C" void kernel_launch(void* const* d_in, const int* in_sizes, int n_in,
                              void* d_out, int out_size) {
    const float* o1    = (const float*)d_in[0];
    const float* o2    = (const float*)d_in[1];
    const float* o3    = (const float*)d_in[2];
    const float* o4    = (const float*)d_in[3];
    const float* o5    = (const float*)d_in[4];
    const float* o6    = (const float*)d_in[5];
    const float* mimic = (const float*)d_in[6];
    const int*   tgt   = (const int*)d_in[7];

    const int N = in_sizes[7];            // 16384 rows
    const int C = in_sizes[0] / N;        // 1000 classes

    float* out = (float*)d_out;           // [0]=max_preds, [1..]=thresholds [N,7]

    if (C == 1000) {
        fused_kernel<250><<<N, 224>>>(o1, o2, o3, o4, o5, o6, mimic, tgt,
                                      out + 1, out, C);
    } else {
        fused_kernel_gen<<<N, 224>>>(o1, o2, o3, o4, o5, o6, mimic, tgt,
                                     out + 1, out, C);
    }
}

// round 8
// speedup vs baseline: 1.0462x; 1.0462x over previous
#include <cuda_runtime.h>
#include <math_constants.h>

#define MAX_N      65536
#define MAX_BLOCKS 65536
__device__ float    g_margin[MAX_N * 7];   // pre-scaled margins (m/2); overwritten each call
__device__ float    g_partial[MAX_BLOCKS]; // per-scan-block head max; overwritten each call
__device__ unsigned g_maxu;                // ordered-uint max; reset by last finalize block
__device__ unsigned g_count;               // reset by last finalize block

__device__ __forceinline__ unsigned order_f32(float f) {
    unsigned u = __float_as_uint(f);
    return (u & 0x80000000u) ? ~u : (u | 0x80000000u);
}
__device__ __forceinline__ float unorder_f32(unsigned u) {
    return __uint_as_float((u & 0x80000000u) ? (u ^ 0x80000000u) : ~u);
}
__device__ __forceinline__ void top2_update(float& t1, float& t2, float v) {
    t2 = fmaxf(t2, fminf(t1, v));
    t1 = fmaxf(t1, v);
}

// ---------- Kernel A (unchanged from R6): one warp per (row, head) ----------
template<int NV4>   // NV4 = C/4
__global__ __launch_bounds__(256) void scan_kernel(
    const float* __restrict__ o1, const float* __restrict__ o2,
    const float* __restrict__ o3, const float* __restrict__ o4,
    const float* __restrict__ o5, const float* __restrict__ o6,
    const float* __restrict__ mimic,
    const int* __restrict__ targets,
    int C, int N)
{
    const int wid  = threadIdx.x >> 5;
    const int lane = threadIdx.x & 31;
    const int gw   = (blockIdx.x << 3) + wid;
    const int total = N * 7;

    __shared__ float s_top1[8];
    s_top1[wid] = -CUDART_INF_F;

    if (gw < total) {
        const int row = gw / 7;
        const int h   = gw - row * 7;

        const float* heads[7] = {o1, o2, o3, o4, o5, o6, mimic};
        const float* p = heads[h] + (size_t)row * (size_t)C;
        const float4* p4 = (const float4*)p;

        const int tgt = targets[row];
        float tval = (lane == 0) ? __ldg(p + tgt) : 0.0f;

        constexpr int K = (NV4 + 31) / 32;   // 8 for NV4=250
        float4 v[K];
        #pragma unroll
        for (int k = 0; k < K; ++k) {
            int idx = lane + 32 * k;
            if (32 * k + 31 < NV4 || idx < NV4)
                v[k] = __ldcs(p4 + idx);
            else
                v[k] = make_float4(-CUDART_INF_F, -CUDART_INF_F,
                                   -CUDART_INF_F, -CUDART_INF_F);
        }

        float t1 = -CUDART_INF_F, t2 = -CUDART_INF_F;
        #pragma unroll
        for (int k = 0; k < K; ++k) {
            top2_update(t1, t2, v[k].x);
            top2_update(t1, t2, v[k].y);
            top2_update(t1, t2, v[k].z);
            top2_update(t1, t2, v[k].w);
        }

        #pragma unroll
        for (int off = 16; off; off >>= 1) {
            float u1 = __shfl_down_sync(0xFFFFFFFFu, t1, off);
            float u2 = __shfl_down_sync(0xFFFFFFFFu, t2, off);
            t2 = fmaxf(fmaxf(t2, u2), fminf(t1, u1));
            t1 = fmaxf(t1, u1);
        }

        if (lane == 0) {
            g_margin[gw] = (tval == t1) ? (t1 - t2) * 0.5f : 0.0f;
            if (h < 6) s_top1[wid] = t1;
        }
    }
    __syncthreads();

    if (threadIdx.x == 0) {
        float bm = s_top1[0];
        #pragma unroll
        for (int w = 1; w < 8; ++w) bm = fmaxf(bm, s_top1[w]);
        g_partial[blockIdx.x] = bm;
    }
}

__global__ __launch_bounds__(256) void scan_kernel_gen(
    const float* __restrict__ o1, const float* __restrict__ o2,
    const float* __restrict__ o3, const float* __restrict__ o4,
    const float* __restrict__ o5, const float* __restrict__ o6,
    const float* __restrict__ mimic,
    const int* __restrict__ targets,
    int C, int N)
{
    const int wid  = threadIdx.x >> 5;
    const int lane = threadIdx.x & 31;
    const int gw   = (blockIdx.x << 3) + wid;
    const int total = N * 7;

    __shared__ float s_top1[8];
    s_top1[wid] = -CUDART_INF_F;

    if (gw < total) {
        const int row = gw / 7;
        const int h   = gw - row * 7;
        const float* heads[7] = {o1, o2, o3, o4, o5, o6, mimic};
        const float* p = heads[h] + (size_t)row * (size_t)C;

        const int tgt = targets[row];
        float tval = (lane == 0) ? __ldg(p + tgt) : 0.0f;

        float t1 = -CUDART_INF_F, t2 = -CUDART_INF_F;
        const int nv4 = C >> 2;
        const float4* p4 = (const float4*)p;
        for (int i = lane; i < nv4; i += 32) {
            float4 v = __ldcs(p4 + i);
            top2_update(t1, t2, v.x); top2_update(t1, t2, v.y);
            top2_update(t1, t2, v.z); top2_update(t1, t2, v.w);
        }
        for (int i = (nv4 << 2) + lane; i < C; i += 32)
            top2_update(t1, t2, p[i]);

        #pragma unroll
        for (int off = 16; off; off >>= 1) {
            float u1 = __shfl_down_sync(0xFFFFFFFFu, t1, off);
            float u2 = __shfl_down_sync(0xFFFFFFFFu, t2, off);
            t2 = fmaxf(fmaxf(t2, u2), fminf(t1, u1));
            t1 = fmaxf(t1, u1);
        }
        if (lane == 0) {
            g_margin[gw] = (tval == t1) ? (t1 - t2) * 0.5f : 0.0f;
            if (h < 6) s_top1[wid] = t1;
        }
    }
    __syncthreads();
    if (threadIdx.x == 0) {
        float bm = s_top1[0];
        #pragma unroll
        for (int w = 1; w < 8; ++w) bm = fmaxf(bm, s_top1[w]);
        g_partial[blockIdx.x] = bm;
    }
}

// ---------- Kernel B: coalesced smem-staged softmax + distributed max ----------
// One block per 256 rows. Stage 1792 floats coalesced (L2-hot), softmax per
// thread in smem, write back coalesced. Each block also max-reduces its chunk
// of g_partial; last-done block publishes out[0].
__global__ __launch_bounds__(256) void finalize_kernel(
    float* __restrict__ out,          // out[0]=max, out+1 = thresholds [N,7]
    int N, int npart)
{
    __shared__ float s[256 * 7];

    const int tid  = threadIdx.x;
    const int lane = tid & 31;
    const int rbase = blockIdx.x * 256;          // first row of this block
    const int nrows = min(256, N - rbase);       // rows in this block
    const int nflt  = nrows * 7;

    // coalesced load of margins (written by scan just before -> L2 hit)
    const float* src = g_margin + (size_t)rbase * 7;
    for (int i = tid; i < nflt; i += 256) s[i] = src[i];
    __syncthreads();

    // per-thread softmax in smem
    if (tid < nrows) {
        float m[7], mx = -CUDART_INF_F;
        #pragma unroll
        for (int h = 0; h < 7; ++h) { m[h] = s[tid * 7 + h]; mx = fmaxf(mx, m[h]); }
        float sum = 0.0f, e[7];
        #pragma unroll
        for (int h = 0; h < 7; ++h) { e[h] = __expf(m[h] - mx); sum += e[h]; }
        float inv = 1.0f / sum;
        #pragma unroll
        for (int h = 0; h < 7; ++h) s[tid * 7 + h] = e[h] * inv;
    }
    __syncthreads();

    // coalesced store
    float* dst = out + 1 + (size_t)rbase * 7;
    for (int i = tid; i < nflt; i += 256) dst[i] = s[i];

    // ---- distributed reduction of g_partial ----
    const int chunk = (npart + gridDim.x - 1) / gridDim.x;
    const int pbase = blockIdx.x * chunk;
    const int pend  = min(pbase + chunk, npart);
    float m = -CUDART_INF_F;
    for (int i = pbase + tid; i < pend; i += 256)
        m = fmaxf(m, g_partial[i]);
    #pragma unroll
    for (int off = 16; off; off >>= 1)
        m = fmaxf(m, __shfl_xor_sync(0xFFFFFFFFu, m, off));

    __shared__ float s_w[8];
    if (lane == 0) s_w[tid >> 5] = m;
    __syncthreads();

    if (tid == 0) {
        float bm = s_w[0];
        #pragma unroll
        for (int w = 1; w < 8; ++w) bm = fmaxf(bm, s_w[w]);
        atomicMax(&g_maxu, order_f32(bm));
        __threadfence();
        unsigned old = atomicAdd(&g_count, 1u);
        if (old == gridDim.x - 1) {
            out[0] = unorder_f32(g_maxu);
            g_maxu  = 0u;   // deterministic reset for next graph replay
            g_count = 0u;
        }
    }
}

extern "C" void kernel_launch(void* const* d_in, const int* in_sizes, int n_in,
                              void* d_out, int out_size) {
    const float* o1    = (const float*)d_in[0];
    const float* o2    = (const float*)d_in[1];
    const float* o3    = (const float*)d_in[2];
    const float* o4    = (const float*)d_in[3];
    const float* o5    = (const float*)d_in[4];
    const float* o6    = (const float*)d_in[5];
    const float* mimic = (const float*)d_in[6];
    const int*   tgt   = (const int*)d_in[7];

    const int N = in_sizes[7];            // 16384 rows
    const int C = in_sizes[0] / N;        // 1000 classes

    float* out = (float*)d_out;

    const int total_warps = N * 7;                  // 114688
    int grid = (total_warps + 7) >> 3;              // 14336 blocks of 8 warps
    if (grid > MAX_BLOCKS) grid = MAX_BLOCKS;

    if (C == 1000) {
        scan_kernel<250><<<grid, 256>>>(o1, o2, o3, o4, o5, o6, mimic, tgt, C, N);
    } else {
        scan_kernel_gen<<<grid, 256>>>(o1, o2, o3, o4, o5, o6, mimic, tgt, C, N);
    }

    int fgrid = (N + 255) >> 8;                     // 64 blocks for N=16384
    finalize_kernel<<<fgrid, 256>>>(out, N, grid);
}